// round 1
// baseline (speedup 1.0000x reference)
#include <cuda_runtime.h>
#include <cuda_bf16.h>
#include <math_constants.h>

// Problem dims (fixed by setup_inputs)
#define B_   64
#define C_   16
#define R_   1152
#define I_   64
#define O_   64
#define RT_  144          // r-tiles of 8
#define R_PER_CTA 8

typedef unsigned long long ull;

// ---- scratch (device globals: allocation-free rule) ----
__device__ float g_P[(size_t)C_ * B_ * R_ * O_];            // 302 MB priors
__device__ float g_Spart[(size_t)C_ * RT_ * B_ * O_];       // 37.7 MB weighted partial sums
__device__ float g_m0[C_];
__device__ float g_Z0[C_];

// ---- f32x2 helpers ----
__device__ __forceinline__ ull dup2(float s) {
    ull r; asm("mov.b64 %0, {%1, %1};" : "=l"(r) : "r"(__float_as_uint(s))); return r;
}
__device__ __forceinline__ void fma2(ull& d, ull a, ull b) {
    asm("fma.rn.f32x2 %0, %1, %2, %0;" : "+l"(d) : "l"(a), "l"(b));
}
__device__ __forceinline__ float lo32(ull v) { return __uint_as_float((unsigned)v); }
__device__ __forceinline__ float hi32(ull v) { return __uint_as_float((unsigned)(v >> 32)); }

// ============================================================
// K0: per-capsule softmax stats of route_logits (general; zeros in practice)
// ============================================================
__global__ void cap_k0(const float* __restrict__ l0) {
    int c = blockIdx.x;
    int t = threadIdx.x, lane = t & 31, w = t >> 5;
    __shared__ float sm[4], sz[4], mbc;

    float m = -CUDART_INF_F;
    for (int i = t; i < R_; i += 128) m = fmaxf(m, l0[c * R_ + i]);
    #pragma unroll
    for (int s = 16; s; s >>= 1) m = fmaxf(m, __shfl_xor_sync(0xffffffffu, m, s));
    if (lane == 0) sm[w] = m;
    __syncthreads();
    if (t == 0) mbc = fmaxf(fmaxf(sm[0], sm[1]), fmaxf(sm[2], sm[3]));
    __syncthreads();
    m = mbc;

    float z = 0.f;
    for (int i = t; i < R_; i += 128) z += __expf(l0[c * R_ + i] - m);
    #pragma unroll
    for (int s = 16; s; s >>= 1) z += __shfl_xor_sync(0xffffffffu, z, s);
    if (lane == 0) sz[w] = z;
    __syncthreads();
    if (t == 0) {
        g_m0[c] = m;
        g_Z0[c] = sz[0] + sz[1] + sz[2] + sz[3];
    }
}

// ============================================================
// K1: priors GEMM. CTA = (c, r-tile of 8). For each r:
//   P[c,:,r,:] (64x64) = X[:,r,:] (64x64) @ W[c,r] (64x64), fp32, f32x2 FMAs.
// Also accumulates S_part = sum_r e^{l0-m0} * P tile.
// ============================================================
__global__ void __launch_bounds__(256) cap_k1(
    const float* __restrict__ x,
    const float* __restrict__ w,
    const float* __restrict__ l0)
{
    __shared__ float Xs[64 * 68];   // Xs[i][b], pitch 68 (conflict-free transpose)
    __shared__ float Ws[64 * 64];   // Ws[i][o]

    const int cta = blockIdx.x;
    const int c  = cta / RT_;
    const int rt = cta % RT_;
    const int t  = threadIdx.x;
    const int tn = t & 15;          // 16 n-groups
    const int tm = t >> 4;          // 16 m-groups
    const int m0 = tm * 4;          // batch rows m0..m0+3
    const int n0 = tn * 4;          // o cols  n0..n0+3

    const float m0c = g_m0[c];

    // weighted S accumulators (f32x2 over m-pairs) x 4 n
    ull sacc[2][4];
    #pragma unroll
    for (int a = 0; a < 2; a++)
        #pragma unroll
        for (int b = 0; b < 4; b++) sacc[a][b] = 0ull;

    for (int rr = 0; rr < R_PER_CTA; ++rr) {
        const int r = rt * R_PER_CTA + rr;

        // --- load X[:,r,:] transposed into Xs[i][b] ---
        {
            const int b  = t & 63;
            const int i0 = (t >> 6) << 4;   // 16 i's per thread
            const float4* src = (const float4*)(x + ((size_t)b * R_ + r) * I_ + i0);
            float4 v0 = src[0], v1 = src[1], v2 = src[2], v3 = src[3];
            float* dst = Xs + (size_t)i0 * 68 + b;
            dst[0*68]=v0.x; dst[1*68]=v0.y; dst[2*68]=v0.z; dst[3*68]=v0.w;
            dst[4*68]=v1.x; dst[5*68]=v1.y; dst[6*68]=v1.z; dst[7*68]=v1.w;
            dst[8*68]=v2.x; dst[9*68]=v2.y; dst[10*68]=v2.z; dst[11*68]=v2.w;
            dst[12*68]=v3.x; dst[13*68]=v3.y; dst[14*68]=v3.z; dst[15*68]=v3.w;
        }
        // --- load W[c,r] into Ws (contiguous copy) ---
        {
            const float4* src = (const float4*)(w + ((size_t)c * R_ + r) * I_ * O_);
            float4* dst = (float4*)Ws;
            dst[t]       = src[t];
            dst[t + 256] = src[t + 256];
            dst[t + 512] = src[t + 512];
            dst[t + 768] = src[t + 768];
        }
        __syncthreads();

        // --- 64x64x64 GEMM piece: 4m x 4n per thread, f32x2 over m-pairs ---
        ull acc[2][4];
        #pragma unroll
        for (int a = 0; a < 2; a++)
            #pragma unroll
            for (int b = 0; b < 4; b++) acc[a][b] = 0ull;

        #pragma unroll 16
        for (int k = 0; k < 64; ++k) {
            const float* xr = Xs + (size_t)k * 68 + m0;
            ull a01 = *(const ull*)(xr);       // (X[m0][k],  X[m0+1][k])
            ull a23 = *(const ull*)(xr + 2);   // (X[m0+2][k],X[m0+3][k])
            float4 bv = *(const float4*)(Ws + (size_t)k * 64 + n0);
            ull b0 = dup2(bv.x), b1 = dup2(bv.y), b2 = dup2(bv.z), b3 = dup2(bv.w);
            fma2(acc[0][0], a01, b0); fma2(acc[1][0], a23, b0);
            fma2(acc[0][1], a01, b1); fma2(acc[1][1], a23, b1);
            fma2(acc[0][2], a01, b2); fma2(acc[1][2], a23, b2);
            fma2(acc[0][3], a01, b3); fma2(acc[1][3], a23, b3);
        }

        // --- write P tile (4 rows of float4) ---
        #pragma unroll
        for (int j = 0; j < 4; ++j) {
            int mp = j >> 1;
            float4 row;
            if ((j & 1) == 0)
                row = make_float4(lo32(acc[mp][0]), lo32(acc[mp][1]), lo32(acc[mp][2]), lo32(acc[mp][3]));
            else
                row = make_float4(hi32(acc[mp][0]), hi32(acc[mp][1]), hi32(acc[mp][2]), hi32(acc[mp][3]));
            size_t off = (((size_t)(c * B_ + (m0 + j)) * R_ + r)) * O_ + n0;
            *(float4*)(g_P + off) = row;
        }

        // --- accumulate weighted S ---
        {
            float w0 = __expf(l0[c * R_ + r] - m0c);
            ull wd = dup2(w0);
            #pragma unroll
            for (int a = 0; a < 2; a++)
                #pragma unroll
                for (int b = 0; b < 4; b++) fma2(sacc[a][b], wd, acc[a][b]);
        }
        __syncthreads();
    }

    // --- write S_part tile ---
    #pragma unroll
    for (int j = 0; j < 4; ++j) {
        int mp = j >> 1;
        float4 row;
        if ((j & 1) == 0)
            row = make_float4(lo32(sacc[mp][0]), lo32(sacc[mp][1]), lo32(sacc[mp][2]), lo32(sacc[mp][3]));
        else
            row = make_float4(hi32(sacc[mp][0]), hi32(sacc[mp][1]), hi32(sacc[mp][2]), hi32(sacc[mp][3]));
        size_t off = (((size_t)(c * RT_ + rt) * B_ + (m0 + j))) * O_ + n0;
        *(float4*)(g_Spart + off) = row;
    }
}

// ============================================================
// K2: routing. CTA = (c,b). Reduce S_part -> u0, then two online-softmax
// passes over P[c,b] (v = u0, then v = u0+u1). Output = squash(s2).
// Occupancy capped at 2 CTAs/SM so P stays L2-resident between passes.
// ============================================================
__global__ void __launch_bounds__(256, 2) cap_k2(
    const float* __restrict__ l0,
    float* __restrict__ out)
{
    const int b = blockIdx.x & 63;
    const int c = blockIdx.x >> 6;
    const int t = threadIdx.x, lane = t & 31, w = t >> 5;

    __shared__ float l0s[R_];
    __shared__ float sv[O_];
    __shared__ float wm[8], wz[8];
    __shared__ float waccs[8][O_];

    for (int i = t; i < R_; i += 256) l0s[i] = l0[c * R_ + i];

    const float Z0 = g_Z0[c];
    const float* __restrict__ P = g_P + (size_t)(c * B_ + b) * R_ * O_;

    // --- s0 from S_part, u0 = squash(s0) ---
    if (t < 64) {
        const float* sp = g_Spart + ((size_t)c * RT_ * B_ + b) * O_ + t;
        float s = 0.f;
        for (int rt = 0; rt < RT_; ++rt) s += sp[(size_t)rt * B_ * O_];
        sv[t] = s / Z0;
    }
    __syncthreads();

    float2 v2;
    {
        float sq = 0.f;
        #pragma unroll 8
        for (int o = 0; o < O_; ++o) { float s_ = sv[o]; sq += s_ * s_; }
        float scale = (sq / (1.f + sq)) * rsqrtf(sq);
        v2.x = scale * sv[2 * lane];
        v2.y = scale * sv[2 * lane + 1];
    }
    __syncthreads();

    // --- two routing iterations, single-pass online softmax each ---
    for (int it = 0; it < 2; ++it) {
        float m = -CUDART_INF_F, Z = 0.f, ax = 0.f, ay = 0.f;

        for (int r = w; r < R_; r += 16) {       // 2 r's per trip for MLP
            int r2 = r + 8;
            float2 p  = *(const float2*)(P + (size_t)r  * O_ + 2 * lane);
            float2 p2 = *(const float2*)(P + (size_t)r2 * O_ + 2 * lane);

            float d = p.x * v2.x + p.y * v2.y;
            #pragma unroll
            for (int s = 16; s; s >>= 1) d += __shfl_xor_sync(0xffffffffu, d, s);
            float l = l0s[r] + d;
            float mn = fmaxf(m, l);
            float corr = __expf(m - mn);
            float e = __expf(l - mn);
            Z = Z * corr + e; ax = ax * corr + e * p.x; ay = ay * corr + e * p.y; m = mn;

            float d2 = p2.x * v2.x + p2.y * v2.y;
            #pragma unroll
            for (int s = 16; s; s >>= 1) d2 += __shfl_xor_sync(0xffffffffu, d2, s);
            float l2v = l0s[r2] + d2;
            mn = fmaxf(m, l2v);
            corr = __expf(m - mn);
            e = __expf(l2v - mn);
            Z = Z * corr + e; ax = ax * corr + e * p2.x; ay = ay * corr + e * p2.y; m = mn;
        }

        if (lane == 0) { wm[w] = m; wz[w] = Z; }
        waccs[w][2 * lane]     = ax;
        waccs[w][2 * lane + 1] = ay;
        __syncthreads();

        float mstar = wm[0];
        #pragma unroll
        for (int q = 1; q < 8; ++q) mstar = fmaxf(mstar, wm[q]);

        if (t < 64) {
            float sn = 0.f, Zs = 0.f;
            #pragma unroll
            for (int q = 0; q < 8; ++q) {
                float f = __expf(wm[q] - mstar);
                sn += waccs[q][t] * f;
                Zs += wz[q] * f;
            }
            sv[t] = sn / Zs;
        }
        __syncthreads();

        float sq = 0.f;
        #pragma unroll 8
        for (int o = 0; o < O_; ++o) { float s_ = sv[o]; sq += s_ * s_; }
        float scale = (sq / (1.f + sq)) * rsqrtf(sq);

        if (it == 0) {
            v2.x += scale * sv[2 * lane];
            v2.y += scale * sv[2 * lane + 1];
            __syncthreads();   // protect wm/wz/waccs before next pass rewrites
        } else {
            if (t < 64) out[(size_t)(c * B_ + b) * O_ + t] = scale * sv[t];
        }
    }
}

// ============================================================
extern "C" void kernel_launch(void* const* d_in, const int* in_sizes, int n_in,
                              void* d_out, int out_size)
{
    const float* x  = (const float*)d_in[0];   // (B, R, I)
    const float* w  = (const float*)d_in[1];   // (C, R, I, O)
    const float* l0 = (const float*)d_in[2];   // (C, 1, R, 1, 1)
    float* out = (float*)d_out;                // (C, B, 1, 1, O)

    cap_k0<<<C_, 128>>>(l0);
    cap_k1<<<C_ * RT_, 256>>>(x, w, l0);
    cap_k2<<<C_ * B_, 256>>>(l0, out);
}

// round 3
// speedup vs baseline: 1.0307x; 1.0307x over previous
#include <cuda_runtime.h>
#include <cuda_fp16.h>
#include <math_constants.h>

// Problem dims (fixed by setup_inputs)
#define B_   64
#define C_   16
#define R_   1152
#define I_   64
#define O_   64
#define RT_  144          // r-tiles of 8
#define R_PER_CTA 8

typedef unsigned long long ull;

// ---- scratch (device globals: allocation-free rule) ----
__device__ float g_P[(size_t)C_ * B_ * R_ * O_];            // 302 MB priors (fp32)
__device__ float g_Spart[(size_t)C_ * RT_ * B_ * O_];       // 37.7 MB weighted partial sums
__device__ float g_m0[C_];
__device__ float g_Z0[C_];

// ---- f32x2 helpers ----
__device__ __forceinline__ ull dup2(float s) {
    ull r; asm("mov.b64 %0, {%1, %1};" : "=l"(r) : "r"(__float_as_uint(s))); return r;
}
__device__ __forceinline__ void fma2(ull& d, ull a, ull b) {
    asm("fma.rn.f32x2 %0, %1, %2, %0;" : "+l"(d) : "l"(a), "l"(b));
}
__device__ __forceinline__ float lo32(ull v) { return __uint_as_float((unsigned)v); }
__device__ __forceinline__ float hi32(ull v) { return __uint_as_float((unsigned)(v >> 32)); }

// ============================================================
// K0: per-capsule softmax stats of route_logits
// ============================================================
__global__ void cap_k0(const float* __restrict__ l0) {
    int c = blockIdx.x;
    int t = threadIdx.x, lane = t & 31, w = t >> 5;
    __shared__ float sm[4], sz[4], mbc;

    float m = -CUDART_INF_F;
    for (int i = t; i < R_; i += 128) m = fmaxf(m, l0[c * R_ + i]);
    #pragma unroll
    for (int s = 16; s; s >>= 1) m = fmaxf(m, __shfl_xor_sync(0xffffffffu, m, s));
    if (lane == 0) sm[w] = m;
    __syncthreads();
    if (t == 0) mbc = fmaxf(fmaxf(sm[0], sm[1]), fmaxf(sm[2], sm[3]));
    __syncthreads();
    m = mbc;

    float z = 0.f;
    for (int i = t; i < R_; i += 128) z += __expf(l0[c * R_ + i] - m);
    #pragma unroll
    for (int s = 16; s; s >>= 1) z += __shfl_xor_sync(0xffffffffu, z, s);
    if (lane == 0) sz[w] = z;
    __syncthreads();
    if (t == 0) {
        g_m0[c] = m;
        g_Z0[c] = sz[0] + sz[1] + sz[2] + sz[3];
    }
}

// ============================================================
// K1: priors GEMM. CTA = (c-pair, r-tile of 8).
// Per r: tile M=64(b) x N=128(2c x 64o), K=64, fp32 f32x2 packed over o-pairs.
// Per-thread: 4m x 8o. W double-buffered in 32-k panels; X prefetched.
// P stored fp32; also accumulates Spart = sum_r e^{l0-m0} * P (fp32).
// ============================================================
__global__ void __launch_bounds__(256, 2) cap_k1(
    const float* __restrict__ x,
    const float* __restrict__ w,
    const float* __restrict__ l0)
{
    __shared__ float Xs[64][64];        // [b][i]   16 KB
    __shared__ float Ws[2][32][128];    // [panel][k][n], n = c_local*64+o, 32 KB

    const int cta = blockIdx.x;
    const int cp  = cta / RT_;          // c-pair 0..7
    const int rt  = cta % RT_;
    const int c0  = cp * 2;
    const int t   = threadIdx.x;
    const int tm  = t >> 4;             // 0..15
    const int tn  = t & 15;             // 0..15
    const int m0  = tm * 4;             // 4 batch rows
    const int c_local = tn >> 3;
    const int o0  = (tn & 7) * 8;       // 8 o's
    const int n0  = c_local * 64 + o0;
    const int c   = c0 + c_local;
    const float m0c = g_m0[c];

    auto ldgX = [&](float4* px, int r) {
        #pragma unroll
        for (int q = 0; q < 4; ++q) {
            int f = t + q * 256;
            int b = f >> 4, i4 = f & 15;
            px[q] = *(const float4*)(x + ((size_t)b * R_ + r) * I_ + i4 * 4);
        }
    };
    auto stsX = [&](const float4* px) {
        #pragma unroll
        for (int q = 0; q < 4; ++q) {
            int f = t + q * 256;
            int b = f >> 4, i4 = f & 15;
            *(float4*)&Xs[b][i4 * 4] = px[q];
        }
    };
    auto ldgW = [&](float4* pw, int r, int k0) {
        #pragma unroll
        for (int q = 0; q < 4; ++q) {
            int f = t + q * 256;
            int k = f >> 5, n4 = f & 31;
            int cl = n4 >> 4, o4 = n4 & 15;
            pw[q] = *(const float4*)(w + ((size_t)(c0 + cl) * R_ + r) * 4096
                                       + (size_t)(k0 + k) * 64 + o4 * 4);
        }
    };
    auto stsW = [&](const float4* pw, int p) {
        #pragma unroll
        for (int q = 0; q < 4; ++q) {
            int f = t + q * 256;
            int k = f >> 5, n4 = f & 31;
            int cl = n4 >> 4, o4 = n4 & 15;
            *(float4*)&Ws[p][k][cl * 64 + o4 * 4] = pw[q];
        }
    };

    ull sacc[4][4];
    #pragma unroll
    for (int j = 0; j < 4; ++j)
        #pragma unroll
        for (int q = 0; q < 4; ++q) sacc[j][q] = 0ull;

    {
        int r = rt * R_PER_CTA;
        float4 tmp[4];
        ldgX(tmp, r);  stsX(tmp);
        ldgW(tmp, r, 0); stsW(tmp, 0);
    }
    __syncthreads();

    for (int rr = 0; rr < R_PER_CTA; ++rr) {
        const int r = rt * R_PER_CTA + rr;
        const bool more = (rr < R_PER_CTA - 1);

        ull acc[4][4];
        #pragma unroll
        for (int j = 0; j < 4; ++j)
            #pragma unroll
            for (int q = 0; q < 4; ++q) acc[j][q] = 0ull;

        float4 pw[4];
        ldgW(pw, r, 32);                 // prefetch panel1

        #pragma unroll 8
        for (int k = 0; k < 32; ++k) {
            ulonglong2 q0 = *(const ulonglong2*)&Ws[0][k][n0];
            ulonglong2 q1 = *(const ulonglong2*)&Ws[0][k][n0 + 4];
            #pragma unroll
            for (int j = 0; j < 4; ++j) {
                ull ad = dup2(Xs[m0 + j][k]);
                fma2(acc[j][0], ad, q0.x); fma2(acc[j][1], ad, q0.y);
                fma2(acc[j][2], ad, q1.x); fma2(acc[j][3], ad, q1.y);
            }
        }
        stsW(pw, 1);
        __syncthreads();

        float4 px[4];
        if (more) ldgX(px, r + 1);       // prefetch next X

        #pragma unroll 8
        for (int k = 0; k < 32; ++k) {
            ulonglong2 q0 = *(const ulonglong2*)&Ws[1][k][n0];
            ulonglong2 q1 = *(const ulonglong2*)&Ws[1][k][n0 + 4];
            #pragma unroll
            for (int j = 0; j < 4; ++j) {
                ull ad = dup2(Xs[m0 + j][32 + k]);
                fma2(acc[j][0], ad, q0.x); fma2(acc[j][1], ad, q0.y);
                fma2(acc[j][2], ad, q1.x); fma2(acc[j][3], ad, q1.y);
            }
        }

        {
            float wv = __expf(l0[c * R_ + r] - m0c);
            ull wd = dup2(wv);
            #pragma unroll
            for (int j = 0; j < 4; ++j)
                #pragma unroll
                for (int q = 0; q < 4; ++q) fma2(sacc[j][q], wd, acc[j][q]);
        }
        __syncthreads();                 // all done reading Xs / Ws

        if (more) stsX(px);
        if (more) ldgW(pw, r + 1, 0);

        // epilogue: P tile fp32 (4 rows x 8 o = 2 float4 each)
        #pragma unroll
        for (int j = 0; j < 4; ++j) {
            size_t off = ((size_t)(c * B_ + (m0 + j)) * R_ + r) * O_ + o0;
            float4 f0 = make_float4(lo32(acc[j][0]), hi32(acc[j][0]),
                                    lo32(acc[j][1]), hi32(acc[j][1]));
            float4 f1 = make_float4(lo32(acc[j][2]), hi32(acc[j][2]),
                                    lo32(acc[j][3]), hi32(acc[j][3]));
            *(float4*)(g_P + off)     = f0;
            *(float4*)(g_P + off + 4) = f1;
        }

        if (more) stsW(pw, 0);
        __syncthreads();
    }

    // Spart tile (fp32)
    #pragma unroll
    for (int j = 0; j < 4; ++j) {
        size_t base = ((size_t)(c * RT_ + rt) * B_ + (m0 + j)) * O_ + o0;
        float4 f0 = make_float4(lo32(sacc[j][0]), hi32(sacc[j][0]),
                                lo32(sacc[j][1]), hi32(sacc[j][1]));
        float4 f1 = make_float4(lo32(sacc[j][2]), hi32(sacc[j][2]),
                                lo32(sacc[j][3]), hi32(sacc[j][3]));
        *(float4*)(g_Spart + base)     = f0;
        *(float4*)(g_Spart + base + 4) = f1;
    }
}

// ============================================================
// K2: routing. CTA = (c,b). Reduce Spart -> u0, then two online-softmax
// passes over fp32 P[c,b] (v = u0, then v = u0+u1), 4-r groups for ILP.
// ============================================================
__global__ void __launch_bounds__(256, 2) cap_k2(
    const float* __restrict__ l0,
    float* __restrict__ out)
{
    const int b = blockIdx.x & 63;
    const int c = blockIdx.x >> 6;
    const int t = threadIdx.x, lane = t & 31, w = t >> 5;

    __shared__ float l0s[R_];
    __shared__ float sv[O_];
    __shared__ float wm[8], wz[8];
    __shared__ float waccs[8][O_];

    for (int i = t; i < R_; i += 256) l0s[i] = l0[c * R_ + i];

    const float Z0 = g_Z0[c];
    const float* __restrict__ P = g_P + (size_t)(c * B_ + b) * R_ * O_;

    // --- s0 from Spart, u0 = squash(s0) ---
    if (t < 64) {
        const float* sp = g_Spart + ((size_t)c * RT_ * B_ + b) * O_ + t;
        float s = 0.f;
        for (int rt = 0; rt < RT_; ++rt) s += sp[(size_t)rt * B_ * O_];
        sv[t] = s / Z0;
    }
    __syncthreads();

    float2 v2;
    {
        float sq = 0.f;
        #pragma unroll 8
        for (int o = 0; o < O_; ++o) { float s_ = sv[o]; sq += s_ * s_; }
        float scale = (sq / (1.f + sq)) * rsqrtf(sq);
        v2.x = scale * sv[2 * lane];
        v2.y = scale * sv[2 * lane + 1];
    }
    __syncthreads();

    // --- two routing iterations ---
    for (int it = 0; it < 2; ++it) {
        float m = -CUDART_INF_F, Z = 0.f, ax = 0.f, ay = 0.f;

        for (int trip = 0; trip < 36; ++trip) {
            const int r0 = trip * 32 + w * 4;

            float2 p[4]; float d[4];
            #pragma unroll
            for (int i = 0; i < 4; ++i) {
                p[i] = *(const float2*)(P + (size_t)(r0 + i) * O_ + 2 * lane);
                d[i] = p[i].x * v2.x + p[i].y * v2.y;
            }
            #pragma unroll
            for (int s = 16; s; s >>= 1) {
                d[0] += __shfl_xor_sync(0xffffffffu, d[0], s);
                d[1] += __shfl_xor_sync(0xffffffffu, d[1], s);
                d[2] += __shfl_xor_sync(0xffffffffu, d[2], s);
                d[3] += __shfl_xor_sync(0xffffffffu, d[3], s);
            }
            float lv0 = l0s[r0 + 0] + d[0];
            float lv1 = l0s[r0 + 1] + d[1];
            float lv2 = l0s[r0 + 2] + d[2];
            float lv3 = l0s[r0 + 3] + d[3];
            float lmax = fmaxf(fmaxf(lv0, lv1), fmaxf(lv2, lv3));
            float mn = fmaxf(m, lmax);
            float corr = __expf(m - mn);
            float e0 = __expf(lv0 - mn), e1 = __expf(lv1 - mn);
            float e2 = __expf(lv2 - mn), e3 = __expf(lv3 - mn);
            Z  = Z  * corr + ((e0 + e1) + (e2 + e3));
            ax = ax * corr + ((e0 * p[0].x + e1 * p[1].x) + (e2 * p[2].x + e3 * p[3].x));
            ay = ay * corr + ((e0 * p[0].y + e1 * p[1].y) + (e2 * p[2].y + e3 * p[3].y));
            m = mn;
        }

        if (lane == 0) { wm[w] = m; wz[w] = Z; }
        waccs[w][2 * lane]     = ax;
        waccs[w][2 * lane + 1] = ay;
        __syncthreads();

        float mstar = wm[0];
        #pragma unroll
        for (int q = 1; q < 8; ++q) mstar = fmaxf(mstar, wm[q]);

        if (t < 64) {
            float sn = 0.f, Zs = 0.f;
            #pragma unroll
            for (int q = 0; q < 8; ++q) {
                float f = __expf(wm[q] - mstar);
                sn += waccs[q][t] * f;
                Zs += wz[q] * f;
            }
            sv[t] = sn / Zs;
        }
        __syncthreads();

        float sq = 0.f;
        #pragma unroll 8
        for (int o = 0; o < O_; ++o) { float s_ = sv[o]; sq += s_ * s_; }
        float scale = (sq / (1.f + sq)) * rsqrtf(sq);

        if (it == 0) {
            v2.x += scale * sv[2 * lane];
            v2.y += scale * sv[2 * lane + 1];
            __syncthreads();
        } else {
            if (t < 64) out[(size_t)(c * B_ + b) * O_ + t] = scale * sv[t];
        }
    }
}

// ============================================================
extern "C" void kernel_launch(void* const* d_in, const int* in_sizes, int n_in,
                              void* d_out, int out_size)
{
    const float* x  = (const float*)d_in[0];   // (B, R, I)
    const float* w  = (const float*)d_in[1];   // (C, R, I, O)
    const float* l0 = (const float*)d_in[2];   // (C, 1, R, 1, 1)
    float* out = (float*)d_out;                // (C, B, 1, 1, O)

    cap_k0<<<C_, 128>>>(l0);
    cap_k1<<<8 * RT_, 256>>>(x, w, l0);
    cap_k2<<<C_ * B_, 256>>>(l0, out);
}

// round 5
// speedup vs baseline: 1.8097x; 1.7558x over previous
#include <cuda_runtime.h>
#include <cuda_bf16.h>
#include <math_constants.h>
#include <cstdint>

// Problem dims (fixed by setup_inputs)
#define B_   64
#define C_   16
#define R_   1152
#define I_   64
#define O_   64
#define RT_  144          // r-tiles of 8
#define R_PER_CTA 8

typedef unsigned long long ull;

// ---- scratch (device globals: allocation-free rule) ----
__device__ float g_P[(size_t)C_ * B_ * R_ * O_];      // 302 MB priors, layout [c][b][r][o]
__device__ float g_Spart[(size_t)C_ * RT_ * B_ * O_]; // 37.7 MB weighted partial sums
__device__ float g_m0[C_];
__device__ float g_Z0[C_];
// Pre-swizzled stacked A tiles: per r, 16 KB = [128 rows (b hi | b lo)][64 k] bf16, SW128
__device__ uint4 g_Xstk[(size_t)R_ * 1024];

// ============================================================
// helpers
// ============================================================
__device__ __forceinline__ uint32_t smem_u32(const void* p) {
    uint32_t a;
    asm("{ .reg .u64 t; cvta.to.shared.u64 t, %1; cvt.u32.u64 %0, t; }" : "=r"(a) : "l"(p));
    return a;
}
__device__ __forceinline__ uint32_t swz(uint32_t b) { return b ^ ((b >> 3) & 0x70); }

__device__ __forceinline__ void ldsm4(uint32_t& r0, uint32_t& r1, uint32_t& r2, uint32_t& r3,
                                      uint32_t addr) {
    asm volatile("ldmatrix.sync.aligned.m8n8.x4.shared.b16 {%0,%1,%2,%3}, [%4];"
                 : "=r"(r0), "=r"(r1), "=r"(r2), "=r"(r3) : "r"(addr));
}
__device__ __forceinline__ void ldsm4t(uint32_t& r0, uint32_t& r1, uint32_t& r2, uint32_t& r3,
                                       uint32_t addr) {
    asm volatile("ldmatrix.sync.aligned.m8n8.x4.trans.shared.b16 {%0,%1,%2,%3}, [%4];"
                 : "=r"(r0), "=r"(r1), "=r"(r2), "=r"(r3) : "r"(addr));
}
__device__ __forceinline__ void mma16816(float* c,
                                         uint32_t a0, uint32_t a1, uint32_t a2, uint32_t a3,
                                         uint32_t b0, uint32_t b1) {
    asm volatile(
        "mma.sync.aligned.m16n8k16.row.col.f32.bf16.bf16.f32 "
        "{%0,%1,%2,%3}, {%4,%5,%6,%7}, {%8,%9}, {%0,%1,%2,%3};"
        : "+f"(c[0]), "+f"(c[1]), "+f"(c[2]), "+f"(c[3])
        : "r"(a0), "r"(a1), "r"(a2), "r"(a3), "r"(b0), "r"(b1));
}

// ---- bf16 residual split ----
__device__ __forceinline__ void split2(float v, unsigned short& h, unsigned short& l) {
    __nv_bfloat16 hb = __float2bfloat16_rn(v);
    float res = v - __bfloat162float(hb);
    h = __bfloat16_as_ushort(hb);
    l = __bfloat16_as_ushort(__float2bfloat16_rn(res));
}

// ============================================================
// K0: per-capsule softmax stats of route_logits
// ============================================================
__global__ void cap_k0(const float* __restrict__ l0) {
    int c = blockIdx.x;
    int t = threadIdx.x, lane = t & 31, w = t >> 5;
    __shared__ float sm[4], sz[4], mbc;

    float m = -CUDART_INF_F;
    for (int i = t; i < R_; i += 128) m = fmaxf(m, l0[c * R_ + i]);
    #pragma unroll
    for (int s = 16; s; s >>= 1) m = fmaxf(m, __shfl_xor_sync(0xffffffffu, m, s));
    if (lane == 0) sm[w] = m;
    __syncthreads();
    if (t == 0) mbc = fmaxf(fmaxf(sm[0], sm[1]), fmaxf(sm[2], sm[3]));
    __syncthreads();
    m = mbc;

    float z = 0.f;
    for (int i = t; i < R_; i += 128) z += __expf(l0[c * R_ + i] - m);
    #pragma unroll
    for (int s = 16; s; s >>= 1) z += __shfl_xor_sync(0xffffffffu, z, s);
    if (lane == 0) sz[w] = z;
    __syncthreads();
    if (t == 0) { g_m0[c] = m; g_Z0[c] = sz[0] + sz[1] + sz[2] + sz[3]; }
}

// ============================================================
// KX: X -> stacked hi/lo bf16 A-tiles, pre-swizzled (SW128).
// ============================================================
__global__ void cap_kx(const float* __restrict__ x) {
    const int r = blockIdx.x;
    const int t = threadIdx.x;
    char* dst = (char*)(g_Xstk + (size_t)r * 1024);
    #pragma unroll
    for (int q = 0; q < 8; ++q) {
        int j = t + q * 128;          // 1024 float4s
        int b = j >> 4, i4 = j & 15;
        float4 v = *(const float4*)(x + ((size_t)b * R_ + r) * I_ + i4 * 4);
        unsigned short h0, h1, h2, h3, l0, l1, l2, l3;
        split2(v.x, h0, l0); split2(v.y, h1, l1);
        split2(v.z, h2, l2); split2(v.w, h3, l3);
        ull hip = (ull)h0 | ((ull)h1 << 16) | ((ull)h2 << 32) | ((ull)h3 << 48);
        ull lop = (ull)l0 | ((ull)l1 << 16) | ((ull)l2 << 32) | ((ull)l3 << 48);
        *(ull*)(dst + swz((unsigned)(b * 128 + 8 * i4)))        = hip;
        *(ull*)(dst + swz((unsigned)((64 + b) * 128 + 8 * i4))) = lop;
    }
}

// ============================================================
// K1: tensor-core priors GEMM via mma.sync bf16, 3-term split.
// CTA = (c, 8-r tile). Per r: P_r(64x64) = X_r @ W_cr with
//   P ~= Xhi*Whi + Xhi*Wlo + Xlo*Whi  (ll term ~1e-5, dropped)
// 8 warps: 4(m) x 2(n), warp tile 16x32, mma.m16n8k16.
// ============================================================
__global__ void __launch_bounds__(256) cap_k1(
    const float* __restrict__ w,
    const float* __restrict__ l0)
{
    __shared__ char A_s[16384];      // 128 rows (b hi|lo) x 64 k bf16, SW128
    __shared__ char Wh_s[8192];      // 64 i x 64 o bf16 hi, SW128
    __shared__ char Wl_s[8192];      // lo

    const int t = threadIdx.x, lane = t & 31, wid = t >> 5;
    const int c  = blockIdx.x / RT_;
    const int rt = blockIdx.x % RT_;
    const int m0 = 16 * (wid & 3);
    const int n0 = 32 * (wid >> 2);
    const float m0c = g_m0[c];

    const uint32_t A_base  = smem_u32(A_s);
    const uint32_t Wh_base = smem_u32(Wh_s);
    const uint32_t Wl_base = smem_u32(Wl_s);

    const int g = lane >> 3, rw = lane & 7;
    // A address pieces: row = rowBase + rw + 8*(g&1); byte col = k0*2 + 16*(g>>1)
    const int a_row_off = rw + 8 * (g & 1);
    const int a_col_off = 16 * (g >> 1);
    // B (trans) pieces: k = k0 + rw + 8*(g&1); n = n0sel + 8*(g>>1)
    const int b_k_off = rw + 8 * (g & 1);
    const int b_n_off = 8 * (g >> 1);

    float acc[4][4];
    float sacc[4][4];
    #pragma unroll
    for (int nt = 0; nt < 4; ++nt)
        #pragma unroll
        for (int i = 0; i < 4; ++i) sacc[nt][i] = 0.f;

    // ---- gmem staging ----
    uint4  px[4];
    float4 pw[4];
    auto ldg_r = [&](int r) {
        const uint4* xs = g_Xstk + (size_t)r * 1024;
        const float4* ws = (const float4*)(w + ((size_t)c * R_ + r) * 4096);
        #pragma unroll
        for (int q = 0; q < 4; ++q) { px[q] = xs[t + 256 * q]; pw[q] = ws[t + 256 * q]; }
    };
    auto sts_r = [&]() {
        uint4* ad = (uint4*)A_s;
        #pragma unroll
        for (int q = 0; q < 4; ++q) ad[t + 256 * q] = px[q];
        #pragma unroll
        for (int q = 0; q < 4; ++q) {
            int j = t + q * 256;
            int i = j >> 4, o4 = j & 15;
            unsigned short h0, h1, h2, h3, l0b, l1b, l2b, l3b;
            split2(pw[q].x, h0, l0b); split2(pw[q].y, h1, l1b);
            split2(pw[q].z, h2, l2b); split2(pw[q].w, h3, l3b);
            ull hip = (ull)h0 | ((ull)h1 << 16) | ((ull)h2 << 32) | ((ull)h3 << 48);
            ull lop = (ull)l0b | ((ull)l1b << 16) | ((ull)l2b << 32) | ((ull)l3b << 48);
            uint32_t off = swz((unsigned)(i * 128 + 8 * o4));
            *(ull*)(Wh_s + off) = hip;
            *(ull*)(Wl_s + off) = lop;
        }
    };

    ldg_r(rt * R_PER_CTA);
    sts_r();
    __syncthreads();

    for (int rr = 0; rr < R_PER_CTA; ++rr) {
        const int r = rt * R_PER_CTA + rr;
        const bool more = (rr < R_PER_CTA - 1);

        if (more) ldg_r(r + 1);      // overlap gmem with mma

        #pragma unroll
        for (int nt = 0; nt < 4; ++nt)
            #pragma unroll
            for (int i = 0; i < 4; ++i) acc[nt][i] = 0.f;

        #pragma unroll
        for (int kc = 0; kc < 4; ++kc) {
            const int kb = kc * 32;  // byte offset of k0
            uint32_t ah0, ah1, ah2, ah3, al0, al1, al2, al3;
            ldsm4(ah0, ah1, ah2, ah3,
                  A_base + swz((unsigned)((m0 + a_row_off) * 128 + kb + a_col_off)));
            ldsm4(al0, al1, al2, al3,
                  A_base + swz((unsigned)((64 + m0 + a_row_off) * 128 + kb + a_col_off)));

            uint32_t bh[8], bl[8];
            {
                const int krow = kc * 16 + b_k_off;
                uint32_t offA = swz((unsigned)(krow * 128 + (n0 + b_n_off) * 2));
                uint32_t offB = swz((unsigned)(krow * 128 + (n0 + 16 + b_n_off) * 2));
                ldsm4t(bh[0], bh[1], bh[2], bh[3], Wh_base + offA);
                ldsm4t(bh[4], bh[5], bh[6], bh[7], Wh_base + offB);
                ldsm4t(bl[0], bl[1], bl[2], bl[3], Wl_base + offA);
                ldsm4t(bl[4], bl[5], bl[6], bl[7], Wl_base + offB);
            }
            #pragma unroll
            for (int nt = 0; nt < 4; ++nt) {
                mma16816(acc[nt], ah0, ah1, ah2, ah3, bh[2 * nt], bh[2 * nt + 1]);
                mma16816(acc[nt], ah0, ah1, ah2, ah3, bl[2 * nt], bl[2 * nt + 1]);
                mma16816(acc[nt], al0, al1, al2, al3, bh[2 * nt], bh[2 * nt + 1]);
            }
        }

        // epilogue: STG P fragments + weighted Spart accumulation
        {
            const float wv = __expf(l0[c * R_ + r] - m0c);
            const int row = m0 + (lane >> 2);
            #pragma unroll
            for (int nt = 0; nt < 4; ++nt) {
                const int col = n0 + 8 * nt + 2 * (lane & 3);
                size_t off1 = ((size_t)(c * B_ + row) * R_ + r) * O_ + col;
                size_t off2 = off1 + (size_t)8 * R_ * O_;
                *(float2*)(g_P + off1) = make_float2(acc[nt][0], acc[nt][1]);
                *(float2*)(g_P + off2) = make_float2(acc[nt][2], acc[nt][3]);
                sacc[nt][0] += wv * acc[nt][0];
                sacc[nt][1] += wv * acc[nt][1];
                sacc[nt][2] += wv * acc[nt][2];
                sacc[nt][3] += wv * acc[nt][3];
            }
        }
        __syncthreads();             // done reading smem for this r
        if (more) {
            sts_r();
            __syncthreads();
        }
    }

    // Spart fragments
    {
        const int row = m0 + (lane >> 2);
        #pragma unroll
        for (int nt = 0; nt < 4; ++nt) {
            const int col = n0 + 8 * nt + 2 * (lane & 3);
            size_t base1 = (((size_t)c * RT_ + rt) * B_ + row) * O_ + col;
            size_t base2 = base1 + (size_t)8 * O_;
            *(float2*)(g_Spart + base1) = make_float2(sacc[nt][0], sacc[nt][1]);
            *(float2*)(g_Spart + base2) = make_float2(sacc[nt][2], sacc[nt][3]);
        }
    }
}

// ============================================================
// K2: routing. CTA = (c,b). Reduce Spart -> u0, then two online-softmax
// passes over fp32 P (layout [c][b][r][o]).
// ============================================================
__global__ void __launch_bounds__(256, 2) cap_k2(
    const float* __restrict__ l0,
    float* __restrict__ out)
{
    const int b = blockIdx.x & 63;
    const int c = blockIdx.x >> 6;
    const int t = threadIdx.x, lane = t & 31, w = t >> 5;

    __shared__ float l0s[R_];
    __shared__ float sv[O_];
    __shared__ float wm[8], wz[8];
    __shared__ float waccs[8][O_];

    for (int i = t; i < R_; i += 256) l0s[i] = l0[c * R_ + i];

    const float Z0 = g_Z0[c];
    const float* __restrict__ P = g_P + (size_t)(c * B_ + b) * R_ * O_;

    if (t < 64) {
        const float* sp = g_Spart + ((size_t)c * RT_ * B_ + b) * O_ + t;
        float s = 0.f;
        for (int rt = 0; rt < RT_; ++rt) s += sp[(size_t)rt * B_ * O_];
        sv[t] = s / Z0;
    }
    __syncthreads();

    float2 v2;
    {
        float sq = 0.f;
        #pragma unroll 8
        for (int o = 0; o < O_; ++o) { float s_ = sv[o]; sq += s_ * s_; }
        float scale = (sq / (1.f + sq)) * rsqrtf(sq);
        v2.x = scale * sv[2 * lane];
        v2.y = scale * sv[2 * lane + 1];
    }
    __syncthreads();

    for (int it = 0; it < 2; ++it) {
        float m = -CUDART_INF_F, Z = 0.f, ax = 0.f, ay = 0.f;

        for (int trip = 0; trip < 36; ++trip) {
            const int r0 = trip * 32 + w * 4;

            float2 p[4]; float d[4];
            #pragma unroll
            for (int i = 0; i < 4; ++i) {
                p[i] = *(const float2*)(P + (size_t)(r0 + i) * O_ + 2 * lane);
                d[i] = p[i].x * v2.x + p[i].y * v2.y;
            }
            #pragma unroll
            for (int s = 16; s; s >>= 1) {
                d[0] += __shfl_xor_sync(0xffffffffu, d[0], s);
                d[1] += __shfl_xor_sync(0xffffffffu, d[1], s);
                d[2] += __shfl_xor_sync(0xffffffffu, d[2], s);
                d[3] += __shfl_xor_sync(0xffffffffu, d[3], s);
            }
            float lv0 = l0s[r0 + 0] + d[0];
            float lv1 = l0s[r0 + 1] + d[1];
            float lv2 = l0s[r0 + 2] + d[2];
            float lv3 = l0s[r0 + 3] + d[3];
            float lmax = fmaxf(fmaxf(lv0, lv1), fmaxf(lv2, lv3));
            float mn = fmaxf(m, lmax);
            float corr = __expf(m - mn);
            float e0 = __expf(lv0 - mn), e1 = __expf(lv1 - mn);
            float e2 = __expf(lv2 - mn), e3 = __expf(lv3 - mn);
            Z  = Z  * corr + ((e0 + e1) + (e2 + e3));
            ax = ax * corr + ((e0 * p[0].x + e1 * p[1].x) + (e2 * p[2].x + e3 * p[3].x));
            ay = ay * corr + ((e0 * p[0].y + e1 * p[1].y) + (e2 * p[2].y + e3 * p[3].y));
            m = mn;
        }

        if (lane == 0) { wm[w] = m; wz[w] = Z; }
        waccs[w][2 * lane]     = ax;
        waccs[w][2 * lane + 1] = ay;
        __syncthreads();

        float mstar = wm[0];
        #pragma unroll
        for (int q = 1; q < 8; ++q) mstar = fmaxf(mstar, wm[q]);

        if (t < 64) {
            float sn = 0.f, Zs = 0.f;
            #pragma unroll
            for (int q = 0; q < 8; ++q) {
                float f = __expf(wm[q] - mstar);
                sn += waccs[q][t] * f;
                Zs += wz[q] * f;
            }
            sv[t] = sn / Zs;
        }
        __syncthreads();

        float sq = 0.f;
        #pragma unroll 8
        for (int o = 0; o < O_; ++o) { float s_ = sv[o]; sq += s_ * s_; }
        float scale = (sq / (1.f + sq)) * rsqrtf(sq);

        if (it == 0) {
            v2.x += scale * sv[2 * lane];
            v2.y += scale * sv[2 * lane + 1];
            __syncthreads();
        } else {
            if (t < 64) out[(size_t)(c * B_ + b) * O_ + t] = scale * sv[t];
        }
    }
}

// ============================================================
extern "C" void kernel_launch(void* const* d_in, const int* in_sizes, int n_in,
                              void* d_out, int out_size)
{
    const float* x  = (const float*)d_in[0];   // (B, R, I)
    const float* w  = (const float*)d_in[1];   // (C, R, I, O)
    const float* l0 = (const float*)d_in[2];   // (C, 1, R, 1, 1)
    float* out = (float*)d_out;                // (C, B, 1, 1, O)

    cap_k0<<<C_, 128>>>(l0);
    cap_kx<<<R_, 128>>>(x);
    cap_k1<<<C_ * RT_, 256>>>(w, l0);
    cap_k2<<<C_ * B_, 256>>>(l0, out);
}

// round 6
// speedup vs baseline: 1.9712x; 1.0893x over previous
#include <cuda_runtime.h>
#include <cuda_bf16.h>
#include <math_constants.h>
#include <cstdint>

// Problem dims (fixed by setup_inputs)
#define B_   64
#define C_   16
#define R_   1152
#define I_   64
#define O_   64
#define RT_  144          // r-tiles of 8
#define R_PER_CTA 8

typedef unsigned long long ull;

// ---- scratch (device globals: allocation-free rule) ----
__device__ float g_P[(size_t)C_ * B_ * R_ * O_];      // 302 MB priors, layout [c][b][r][o]
__device__ float g_Spart[(size_t)C_ * RT_ * B_ * O_]; // 37.7 MB weighted partial sums
__device__ float g_m0[C_];
__device__ float g_Z0[C_];
// Pre-swizzled stacked A tiles: per r, 16 KB = [128 rows (b hi | b lo)][64 k] bf16, SW128
__device__ uint4 g_Xstk[(size_t)R_ * 1024];

// ============================================================
// helpers
// ============================================================
__device__ __forceinline__ uint32_t smem_u32(const void* p) {
    uint32_t a;
    asm("{ .reg .u64 t; cvta.to.shared.u64 t, %1; cvt.u32.u64 %0, t; }" : "=r"(a) : "l"(p));
    return a;
}
__device__ __forceinline__ uint32_t swz(uint32_t b) { return b ^ ((b >> 3) & 0x70); }

__device__ __forceinline__ void cp16(uint32_t dst, const void* src) {
    asm volatile("cp.async.cg.shared.global [%0], [%1], 16;" :: "r"(dst), "l"(src));
}
#define CP_COMMIT() asm volatile("cp.async.commit_group;" ::: "memory")
#define CP_WAIT0()  asm volatile("cp.async.wait_group 0;" ::: "memory")

__device__ __forceinline__ void ldsm4(uint32_t& r0, uint32_t& r1, uint32_t& r2, uint32_t& r3,
                                      uint32_t addr) {
    asm volatile("ldmatrix.sync.aligned.m8n8.x4.shared.b16 {%0,%1,%2,%3}, [%4];"
                 : "=r"(r0), "=r"(r1), "=r"(r2), "=r"(r3) : "r"(addr));
}
__device__ __forceinline__ void ldsm4t(uint32_t& r0, uint32_t& r1, uint32_t& r2, uint32_t& r3,
                                       uint32_t addr) {
    asm volatile("ldmatrix.sync.aligned.m8n8.x4.trans.shared.b16 {%0,%1,%2,%3}, [%4];"
                 : "=r"(r0), "=r"(r1), "=r"(r2), "=r"(r3) : "r"(addr));
}
__device__ __forceinline__ void mma16816(float* c,
                                         uint32_t a0, uint32_t a1, uint32_t a2, uint32_t a3,
                                         uint32_t b0, uint32_t b1) {
    asm volatile(
        "mma.sync.aligned.m16n8k16.row.col.f32.bf16.bf16.f32 "
        "{%0,%1,%2,%3}, {%4,%5,%6,%7}, {%8,%9}, {%0,%1,%2,%3};"
        : "+f"(c[0]), "+f"(c[1]), "+f"(c[2]), "+f"(c[3])
        : "r"(a0), "r"(a1), "r"(a2), "r"(a3), "r"(b0), "r"(b1));
}

// ---- bf16 residual split ----
__device__ __forceinline__ void split2(float v, unsigned short& h, unsigned short& l) {
    __nv_bfloat16 hb = __float2bfloat16_rn(v);
    float res = v - __bfloat162float(hb);
    h = __bfloat16_as_ushort(hb);
    l = __bfloat16_as_ushort(__float2bfloat16_rn(res));
}

// ============================================================
// KX: X -> stacked hi/lo bf16 A-tiles, pre-swizzled (SW128).
// Blocks 0..15 additionally compute per-capsule softmax stats of l0.
// ============================================================
__global__ void cap_kx(const float* __restrict__ x, const float* __restrict__ l0) {
    const int r = blockIdx.x;
    const int t = threadIdx.x;
    char* dst = (char*)(g_Xstk + (size_t)r * 1024);
    #pragma unroll
    for (int q = 0; q < 8; ++q) {
        int j = t + q * 128;          // 1024 float4s
        int b = j >> 4, i4 = j & 15;
        float4 v = *(const float4*)(x + ((size_t)b * R_ + r) * I_ + i4 * 4);
        unsigned short h0, h1, h2, h3, l0b, l1b, l2b, l3b;
        split2(v.x, h0, l0b); split2(v.y, h1, l1b);
        split2(v.z, h2, l2b); split2(v.w, h3, l3b);
        ull hip = (ull)h0 | ((ull)h1 << 16) | ((ull)h2 << 32) | ((ull)h3 << 48);
        ull lop = (ull)l0b | ((ull)l1b << 16) | ((ull)l2b << 32) | ((ull)l3b << 48);
        *(ull*)(dst + swz((unsigned)(b * 128 + 8 * i4)))        = hip;
        *(ull*)(dst + swz((unsigned)((64 + b) * 128 + 8 * i4))) = lop;
    }

    if (r < C_) {
        const int c = r;
        const int lane = t & 31, w = t >> 5;
        __shared__ float sm[4], sz[4], mbc;

        float m = -CUDART_INF_F;
        for (int i = t; i < R_; i += 128) m = fmaxf(m, l0[c * R_ + i]);
        #pragma unroll
        for (int s = 16; s; s >>= 1) m = fmaxf(m, __shfl_xor_sync(0xffffffffu, m, s));
        if (lane == 0) sm[w] = m;
        __syncthreads();
        if (t == 0) mbc = fmaxf(fmaxf(sm[0], sm[1]), fmaxf(sm[2], sm[3]));
        __syncthreads();
        m = mbc;

        float z = 0.f;
        for (int i = t; i < R_; i += 128) z += __expf(l0[c * R_ + i] - m);
        #pragma unroll
        for (int s = 16; s; s >>= 1) z += __shfl_xor_sync(0xffffffffu, z, s);
        if (lane == 0) sz[w] = z;
        __syncthreads();
        if (t == 0) { g_m0[c] = m; g_Z0[c] = sz[0] + sz[1] + sz[2] + sz[3]; }
    }
}

// ============================================================
// K1: tensor-core priors GEMM via mma.sync bf16, 3-term split.
// Double-buffered: cp.async for A tiles, overlapped LDG+split for W.
// One __syncthreads per r.
// ============================================================
__global__ void __launch_bounds__(256) cap_k1(
    const float* __restrict__ w,
    const float* __restrict__ l0)
{
    extern __shared__ char smem[];
    // layout: A0 @0 (16K), A1 @16K, Wh0 @32K (8K), Wl0 @40K, Wh1 @48K, Wl1 @56K
    const uint32_t sb = smem_u32(smem);
    const uint32_t Ab[2]  = { sb,          sb + 16384 };
    const uint32_t Whb[2] = { sb + 32768,  sb + 49152 };
    const uint32_t Wlb[2] = { sb + 40960,  sb + 57344 };
    char* Ap[2]  = { smem,         smem + 16384 };
    char* Whp[2] = { smem + 32768, smem + 49152 };
    char* Wlp[2] = { smem + 40960, smem + 57344 };

    const int t = threadIdx.x, lane = t & 31, wid = t >> 5;
    const int c  = blockIdx.x / RT_;
    const int rt = blockIdx.x % RT_;
    const int m0 = 16 * (wid & 3);
    const int n0 = 32 * (wid >> 2);
    const float m0c = g_m0[c];

    const int g = lane >> 3, rw = lane & 7;
    const int a_row_off = rw + 8 * (g & 1);
    const int a_col_off = 16 * (g >> 1);
    const int b_k_off = rw + 8 * (g & 1);
    const int b_n_off = 8 * (g >> 1);

    float acc[4][4];
    float sacc[4][4];
    #pragma unroll
    for (int nt = 0; nt < 4; ++nt)
        #pragma unroll
        for (int i = 0; i < 4; ++i) sacc[nt][i] = 0.f;

    float4 pw[4];
    auto cpA = [&](int buf, int r) {
        const char* src = (const char*)(g_Xstk + (size_t)r * 1024);
        #pragma unroll
        for (int q = 0; q < 4; ++q)
            cp16(Ab[buf] + t * 16 + q * 4096, src + t * 16 + q * 4096);
        CP_COMMIT();
    };
    auto ldgW = [&](int r) {
        const float4* ws = (const float4*)(w + ((size_t)c * R_ + r) * 4096);
        #pragma unroll
        for (int q = 0; q < 4; ++q) pw[q] = ws[t + 256 * q];
    };
    auto stsW = [&](int buf) {
        #pragma unroll
        for (int q = 0; q < 4; ++q) {
            int j = t + q * 256;
            int i = j >> 4, o4 = j & 15;
            unsigned short h0, h1, h2, h3, l0b, l1b, l2b, l3b;
            split2(pw[q].x, h0, l0b); split2(pw[q].y, h1, l1b);
            split2(pw[q].z, h2, l2b); split2(pw[q].w, h3, l3b);
            ull hip = (ull)h0 | ((ull)h1 << 16) | ((ull)h2 << 32) | ((ull)h3 << 48);
            ull lop = (ull)l0b | ((ull)l1b << 16) | ((ull)l2b << 32) | ((ull)l3b << 48);
            uint32_t off = swz((unsigned)(i * 128 + 8 * o4));
            *(ull*)(Whp[buf] + off) = hip;
            *(ull*)(Wlp[buf] + off) = lop;
        }
    };

    // prolog: stage r0 into buffer 0
    {
        int r0 = rt * R_PER_CTA;
        cpA(0, r0);
        ldgW(r0);
        stsW(0);
        CP_WAIT0();
    }
    __syncthreads();

    for (int rr = 0; rr < R_PER_CTA; ++rr) {
        const int r = rt * R_PER_CTA + rr;
        const int cur = rr & 1, nxt = cur ^ 1;
        const bool more = (rr < R_PER_CTA - 1);

        if (more) {
            cpA(nxt, r + 1);       // async copy next A
            ldgW(r + 1);           // LDG next W (in flight during MMA)
        }

        #pragma unroll
        for (int nt = 0; nt < 4; ++nt)
            #pragma unroll
            for (int i = 0; i < 4; ++i) acc[nt][i] = 0.f;

        #pragma unroll
        for (int kc = 0; kc < 4; ++kc) {
            const int kb = kc * 32;  // byte offset of k0
            uint32_t ah0, ah1, ah2, ah3, al0, al1, al2, al3;
            ldsm4(ah0, ah1, ah2, ah3,
                  Ab[cur] + swz((unsigned)((m0 + a_row_off) * 128 + kb + a_col_off)));
            ldsm4(al0, al1, al2, al3,
                  Ab[cur] + swz((unsigned)((64 + m0 + a_row_off) * 128 + kb + a_col_off)));

            uint32_t bh[8], bl[8];
            {
                const int krow = kc * 16 + b_k_off;
                uint32_t offA = swz((unsigned)(krow * 128 + (n0 + b_n_off) * 2));
                uint32_t offB = swz((unsigned)(krow * 128 + (n0 + 16 + b_n_off) * 2));
                ldsm4t(bh[0], bh[1], bh[2], bh[3], Whb[cur] + offA);
                ldsm4t(bh[4], bh[5], bh[6], bh[7], Whb[cur] + offB);
                ldsm4t(bl[0], bl[1], bl[2], bl[3], Wlb[cur] + offA);
                ldsm4t(bl[4], bl[5], bl[6], bl[7], Wlb[cur] + offB);
            }
            #pragma unroll
            for (int nt = 0; nt < 4; ++nt) {
                mma16816(acc[nt], ah0, ah1, ah2, ah3, bh[2 * nt], bh[2 * nt + 1]);
                mma16816(acc[nt], ah0, ah1, ah2, ah3, bl[2 * nt], bl[2 * nt + 1]);
                mma16816(acc[nt], al0, al1, al2, al3, bh[2 * nt], bh[2 * nt + 1]);
            }
        }

        // epilogue: STG P fragments + weighted Spart accumulation
        {
            const float wv = __expf(l0[c * R_ + r] - m0c);
            const int row = m0 + (lane >> 2);
            #pragma unroll
            for (int nt = 0; nt < 4; ++nt) {
                const int col = n0 + 8 * nt + 2 * (lane & 3);
                size_t off1 = ((size_t)(c * B_ + row) * R_ + r) * O_ + col;
                size_t off2 = off1 + (size_t)8 * R_ * O_;
                *(float2*)(g_P + off1) = make_float2(acc[nt][0], acc[nt][1]);
                *(float2*)(g_P + off2) = make_float2(acc[nt][2], acc[nt][3]);
                sacc[nt][0] += wv * acc[nt][0];
                sacc[nt][1] += wv * acc[nt][1];
                sacc[nt][2] += wv * acc[nt][2];
                sacc[nt][3] += wv * acc[nt][3];
            }
        }

        if (more) {
            stsW(nxt);             // split+store next W (after MMAs done reading cur)
            CP_WAIT0();            // A[nxt] landed
        }
        __syncthreads();
    }

    // Spart fragments
    {
        const int row = m0 + (lane >> 2);
        #pragma unroll
        for (int nt = 0; nt < 4; ++nt) {
            const int col = n0 + 8 * nt + 2 * (lane & 3);
            size_t base1 = (((size_t)c * RT_ + rt) * B_ + row) * O_ + col;
            size_t base2 = base1 + (size_t)8 * O_;
            *(float2*)(g_Spart + base1) = make_float2(sacc[nt][0], sacc[nt][1]);
            *(float2*)(g_Spart + base2) = make_float2(sacc[nt][2], sacc[nt][3]);
        }
    }
}

// ============================================================
// K2: routing. CTA = (c,b). 16 streams = 8 warps x 2 half-warps.
// Each lane owns an o-slice of 4 (float4); dot reduce = 4 SHFLs over
// 16 lanes for 2 rows at once; per-lane float4 accumulators.
// ============================================================
__global__ void __launch_bounds__(256, 3) cap_k2(
    const float* __restrict__ l0,
    float* __restrict__ out)
{
    const int b = blockIdx.x & 63;
    const int c = blockIdx.x >> 6;
    const int t = threadIdx.x, lane = t & 31, w = t >> 5;
    const int half = lane >> 4, ln16 = lane & 15;
    const int stream = w * 2 + half;

    __shared__ float l0s[R_];
    __shared__ __align__(16) float sv[O_];
    __shared__ float wm[16], wz[16];
    __shared__ __align__(16) float waccs[16][O_];

    for (int i = t; i < R_; i += 256) l0s[i] = l0[c * R_ + i];

    const float Z0 = g_Z0[c];
    const float* __restrict__ P = g_P + (size_t)(c * B_ + b) * R_ * O_;

    // --- s0 from Spart ---
    if (t < 64) {
        const float* sp = g_Spart + ((size_t)c * RT_ * B_ + b) * O_ + t;
        float s = 0.f;
        for (int rt = 0; rt < RT_; ++rt) s += sp[(size_t)rt * B_ * O_];
        sv[t] = s / Z0;
    }
    __syncthreads();

    float4 v4;
    {
        float sq = 0.f;
        #pragma unroll 8
        for (int o = 0; o < O_; ++o) { float s_ = sv[o]; sq += s_ * s_; }
        float scale = (sq / (1.f + sq)) * rsqrtf(sq);
        float4 s4 = *(const float4*)(sv + 4 * ln16);
        v4.x = scale * s4.x; v4.y = scale * s4.y;
        v4.z = scale * s4.z; v4.w = scale * s4.w;
    }
    __syncthreads();

    for (int it = 0; it < 2; ++it) {
        float m = -CUDART_INF_F, Z = 0.f;
        float4 acc = make_float4(0.f, 0.f, 0.f, 0.f);

        #pragma unroll 4
        for (int step = 0; step < 36; ++step) {
            const int r0 = step * 32 + w * 4 + half * 2;
            const float* p0 = P + (size_t)r0 * O_ + 4 * ln16;
            float4 a = *(const float4*)(p0);
            float4 bq = *(const float4*)(p0 + O_);

            float d0 = a.x * v4.x + a.y * v4.y + a.z * v4.z + a.w * v4.w;
            float d1 = bq.x * v4.x + bq.y * v4.y + bq.z * v4.z + bq.w * v4.w;
            #pragma unroll
            for (int s = 8; s; s >>= 1) {
                d0 += __shfl_xor_sync(0xffffffffu, d0, s);
                d1 += __shfl_xor_sync(0xffffffffu, d1, s);
            }
            float lv0 = l0s[r0] + d0;
            float lv1 = l0s[r0 + 1] + d1;
            float mn = fmaxf(m, fmaxf(lv0, lv1));
            float corr = __expf(m - mn);
            float e0 = __expf(lv0 - mn);
            float e1 = __expf(lv1 - mn);
            Z = Z * corr + (e0 + e1);
            acc.x = acc.x * corr + e0 * a.x + e1 * bq.x;
            acc.y = acc.y * corr + e0 * a.y + e1 * bq.y;
            acc.z = acc.z * corr + e0 * a.z + e1 * bq.z;
            acc.w = acc.w * corr + e0 * a.w + e1 * bq.w;
            m = mn;
        }

        if (ln16 == 0) { wm[stream] = m; wz[stream] = Z; }
        *(float4*)(&waccs[stream][4 * ln16]) = acc;
        __syncthreads();

        float mstar = wm[0];
        #pragma unroll
        for (int q = 1; q < 16; ++q) mstar = fmaxf(mstar, wm[q]);

        if (t < 64) {
            float sn = 0.f, Zs = 0.f;
            #pragma unroll
            for (int q = 0; q < 16; ++q) {
                float f = __expf(wm[q] - mstar);
                sn += waccs[q][t] * f;
                Zs += wz[q] * f;
            }
            sv[t] = sn / Zs;
        }
        __syncthreads();

        float sq = 0.f;
        #pragma unroll 8
        for (int o = 0; o < O_; ++o) { float s_ = sv[o]; sq += s_ * s_; }
        float scale = (sq / (1.f + sq)) * rsqrtf(sq);

        if (it == 0) {
            float4 s4 = *(const float4*)(sv + 4 * ln16);
            v4.x += scale * s4.x; v4.y += scale * s4.y;
            v4.z += scale * s4.z; v4.w += scale * s4.w;
            __syncthreads();
        } else {
            if (t < 64) out[(size_t)(c * B_ + b) * O_ + t] = scale * sv[t];
        }
    }
}

// ============================================================
extern "C" void kernel_launch(void* const* d_in, const int* in_sizes, int n_in,
                              void* d_out, int out_size)
{
    const float* x  = (const float*)d_in[0];   // (B, R, I)
    const float* w  = (const float*)d_in[1];   // (C, R, I, O)
    const float* l0 = (const float*)d_in[2];   // (C, 1, R, 1, 1)
    float* out = (float*)d_out;                // (C, B, 1, 1, O)

    const int K1_SMEM = 65536;
    cudaFuncSetAttribute(cap_k1, cudaFuncAttributeMaxDynamicSharedMemorySize, K1_SMEM);

    cap_kx<<<R_, 128>>>(x, l0);
    cap_k1<<<C_ * RT_, 256, K1_SMEM>>>(w, l0);
    cap_k2<<<C_ * B_, 256>>>(l0, out);
}